// round 1
// baseline (speedup 1.0000x reference)
#include <cuda_runtime.h>

// MatrixExp: Y = X @ exp(S), S = antisym from S_flat, via scaling-and-squaring:
//   E = P6(S/2)  (degree-6 Taylor of exp at S/2; ||S/2|| ~ 0.45 -> err ~1e-6)
//   F = E - I = S/2 + S^2/8 + S^3*(I/48 + S/384 + S^2/3840 + S^3/46080)
//   W = Q - I = (I+F)^2 - I = 2F + F^2
//   Y = X + X*W
// GEMM engine: SIMT fp32 with Blackwell packed fma.rn.f32x2 (2 FMA/issue).

typedef unsigned long long u64;

#define ND 2048
#define NBATCH 8192

// scratch (allocation-free rule: __device__ globals)
__device__ float g_S [ND * ND];
__device__ float g_S2[ND * ND];
__device__ float g_S3[ND * ND];
__device__ float g_W2[ND * ND];
__device__ float g_T [ND * ND];
__device__ float g_W [ND * ND];

__device__ __forceinline__ u64 pk2(float x, float y) {
    u64 r; asm("mov.b64 %0, {%1, %2};" : "=l"(r) : "f"(x), "f"(y)); return r;
}
__device__ __forceinline__ void upk2(u64 v, float &x, float &y) {
    asm("mov.b64 {%0, %1}, %2;" : "=f"(x), "=f"(y) : "l"(v));
}
__device__ __forceinline__ void ffma2(u64 &d, u64 a, u64 b) {
    asm("fma.rn.f32x2 %0, %1, %2, %0;" : "+l"(d) : "l"(a), "l"(b));
}

// Build S[r][c]: +Sf[f(r,c)] above diag, -Sf[f(c,r)] below, 0 on diag.
__global__ void build_S_kernel(float* __restrict__ S, const float* __restrict__ Sf) {
    int idx = blockIdx.x * blockDim.x + threadIdx.x;
    int r = idx >> 11;
    int c = idx & (ND - 1);
    float v = 0.f;
    if (r != c) {
        int rr = r < c ? r : c;
        int cc = r < c ? c : r;
        int f = rr * (2 * ND - rr - 1) / 2 + (cc - rr - 1);
        v = Sf[f];
        if (r > c) v = -v;
    }
    S[idx] = v;
}

// W2 = S3/46080 + S2/3840 + S/384 + I/48 ;  T (Finit) = S2/8 + S/2
__global__ void ew_prep_kernel(float* __restrict__ W2, float* __restrict__ T,
                               const float* __restrict__ S,
                               const float* __restrict__ S2,
                               const float* __restrict__ S3) {
    int idx = blockIdx.x * blockDim.x + threadIdx.x;
    int r = idx >> 11, c = idx & (ND - 1);
    float s = S[idx], s2 = S2[idx], s3 = S3[idx];
    float w2 = s3 * (1.f / 46080.f) + s2 * (1.f / 3840.f) + s * (1.f / 384.f);
    if (r == c) w2 += (1.f / 48.f);
    W2[idx] = w2;
    T[idx] = s2 * 0.125f + s * 0.5f;
}

// C[M,N] = A[M,K] @ B[K,N] + beta * D[M,N]   (D optional)
// 128x128 tile, BK=16, 256 threads, 8x8 micro-tile, fp32x2 packed FMA.
#define BM 128
#define BN 128
#define BK 16
#define LDA 132  // padded (multiple of 4 floats keeps 16B alignment; kills A-store conflicts)

__global__ __launch_bounds__(256) void gemm128(
    float* __restrict__ C,
    const float* __restrict__ A,
    const float* __restrict__ B,
    const float* __restrict__ D,
    float beta, int M, int Nn, int K)
{
    __shared__ __align__(16) float As[BK][LDA];
    __shared__ __align__(16) float Bs[BK][BN];

    const int tid  = threadIdx.x;
    const int lane = tid & 31;
    const int w    = tid >> 5;
    const int m0   = blockIdx.y * BM;
    const int n0   = blockIdx.x * BN;

    // warp covers a 32x64 C patch; lane covers 8x8
    const int tm = (w & 3) * 32 + (lane >> 3) * 8;
    const int tn = (w >> 2) * 64 + (lane & 7) * 8;

    // gmem staging mapping
    const int ar  = tid >> 2;          // A rows ar, ar+64
    const int ac4 = (tid & 3) * 4;     // A cols ac4..ac4+3 within k-tile
    const int br  = tid >> 5;          // B rows br, br+8
    const int bc4 = lane * 4;          // B cols bc4..bc4+3

    const float* pA  = A + (size_t)(m0 + ar) * K + ac4;
    const float* pA2 = pA + (size_t)64 * K;
    const float* pB  = B + (size_t)br * Nn + n0 + bc4;
    const float* pB2 = pB + (size_t)8 * Nn;

    u64 acc[8][4];
#pragma unroll
    for (int i = 0; i < 8; i++)
#pragma unroll
        for (int j = 0; j < 4; j++) acc[i][j] = 0ull;

    const int ktiles = K / BK;

    float4 a0 = *(const float4*)pA;
    float4 a1 = *(const float4*)pA2;
    float4 b0 = *(const float4*)pB;
    float4 b1 = *(const float4*)pB2;

    for (int t = 0; t < ktiles; t++) {
        // stage regs -> smem (A transposed)
        As[ac4 + 0][ar] = a0.x; As[ac4 + 1][ar] = a0.y;
        As[ac4 + 2][ar] = a0.z; As[ac4 + 3][ar] = a0.w;
        As[ac4 + 0][ar + 64] = a1.x; As[ac4 + 1][ar + 64] = a1.y;
        As[ac4 + 2][ar + 64] = a1.z; As[ac4 + 3][ar + 64] = a1.w;
        *(float4*)&Bs[br][bc4]     = b0;
        *(float4*)&Bs[br + 8][bc4] = b1;
        __syncthreads();

        // prefetch next tile (LDG issued before compute, hides latency)
        if (t + 1 < ktiles) {
            pA  += BK; pA2 += BK;
            pB  += (size_t)BK * Nn; pB2 += (size_t)BK * Nn;
            a0 = *(const float4*)pA;
            a1 = *(const float4*)pA2;
            b0 = *(const float4*)pB;
            b1 = *(const float4*)pB2;
        }

#pragma unroll
        for (int kk = 0; kk < BK; kk++) {
            float4 fa0 = *(const float4*)&As[kk][tm];
            float4 fa1 = *(const float4*)&As[kk][tm + 4];
            ulonglong2 fb0 = *(const ulonglong2*)&Bs[kk][tn];
            ulonglong2 fb1 = *(const ulonglong2*)&Bs[kk][tn + 4];
            u64 bd0 = fb0.x, bd1 = fb0.y, bd2 = fb1.x, bd3 = fb1.y;
            u64 ad[8];
            ad[0] = pk2(fa0.x, fa0.x); ad[1] = pk2(fa0.y, fa0.y);
            ad[2] = pk2(fa0.z, fa0.z); ad[3] = pk2(fa0.w, fa0.w);
            ad[4] = pk2(fa1.x, fa1.x); ad[5] = pk2(fa1.y, fa1.y);
            ad[6] = pk2(fa1.z, fa1.z); ad[7] = pk2(fa1.w, fa1.w);
#pragma unroll
            for (int i = 0; i < 8; i++) {
                ffma2(acc[i][0], ad[i], bd0);
                ffma2(acc[i][1], ad[i], bd1);
                ffma2(acc[i][2], ad[i], bd2);
                ffma2(acc[i][3], ad[i], bd3);
            }
        }
        __syncthreads();
    }

    // epilogue: unpack, optional beta*D, vectorized store
#pragma unroll
    for (int i = 0; i < 8; i++) {
        float v[8];
        upk2(acc[i][0], v[0], v[1]);
        upk2(acc[i][1], v[2], v[3]);
        upk2(acc[i][2], v[4], v[5]);
        upk2(acc[i][3], v[6], v[7]);
        size_t off = (size_t)(m0 + tm + i) * Nn + n0 + tn;
        if (D) {
            float4 d0 = *(const float4*)(D + off);
            float4 d1 = *(const float4*)(D + off + 4);
            v[0] += beta * d0.x; v[1] += beta * d0.y;
            v[2] += beta * d0.z; v[3] += beta * d0.w;
            v[4] += beta * d1.x; v[5] += beta * d1.y;
            v[6] += beta * d1.z; v[7] += beta * d1.w;
        }
        float4 o0 = make_float4(v[0], v[1], v[2], v[3]);
        float4 o1 = make_float4(v[4], v[5], v[6], v[7]);
        *(float4*)(C + off)     = o0;
        *(float4*)(C + off + 4) = o1;
    }
}

extern "C" void kernel_launch(void* const* d_in, const int* in_sizes, int n_in,
                              void* d_out, int out_size) {
    const float* X  = (const float*)d_in[0];   // [8192, 2048]
    const float* Sf = (const float*)d_in[1];   // [N*(N-1)/2]
    float* Y = (float*)d_out;                  // [8192, 2048]

    float *S, *S2, *S3, *W2, *T, *W;
    cudaGetSymbolAddress((void**)&S,  g_S);
    cudaGetSymbolAddress((void**)&S2, g_S2);
    cudaGetSymbolAddress((void**)&S3, g_S3);
    cudaGetSymbolAddress((void**)&W2, g_W2);
    cudaGetSymbolAddress((void**)&T,  g_T);
    cudaGetSymbolAddress((void**)&W,  g_W);

    const int EW_BLOCKS = (ND * ND) / 256;
    build_S_kernel<<<EW_BLOCKS, 256>>>(S, Sf);

    dim3 gSq(ND / BN, ND / BM);
    // S2 = S*S ; S3 = S2*S
    gemm128<<<gSq, 256>>>(S2, S, S,  nullptr, 0.f, ND, ND, ND);
    gemm128<<<gSq, 256>>>(S3, S2, S, nullptr, 0.f, ND, ND, ND);
    // W2, Finit
    ew_prep_kernel<<<EW_BLOCKS, 256>>>(W2, T, S, S2, S3);
    // F = S3*W2 + Finit        (stored in W)
    gemm128<<<gSq, 256>>>(W, S3, W2, T, 1.f, ND, ND, ND);
    // Wfull = F*F + 2F         (stored in S2; C distinct from A/B/D)
    gemm128<<<gSq, 256>>>(S2, W, W, W, 2.f, ND, ND, ND);
    // Y = X*Wfull + X
    dim3 gX(ND / BN, NBATCH / BM);
    gemm128<<<gX, 256>>>(Y, X, S2, X, 1.f, NBATCH, ND, ND);
}

// round 6
// speedup vs baseline: 3.8120x; 3.8120x over previous
#include <cuda_runtime.h>
#include <cuda_bf16.h>
#include <cstdint>

typedef unsigned long long u64;

#define ND 2048
#define NB 8192
#define NSQ (ND*ND)

// tcgen05 is arch-SPECIFIC: only available in the sm_103a/sm_100a device pass.
// The harness build also runs a plain compute_103 pass, so guard all tcgen05
// usage and provide a SIMT fallback body for the base target.
#if defined(__CUDA_ARCH__) && (defined(__CUDA_ARCH_FEAT_SM103_ALL) || defined(__CUDA_ARCH_FEAT_SM100_ALL) || defined(__CUDA_ARCH_FEAT_SM101_ALL))
#define HAS_TCGEN05 1
#else
#define HAS_TCGEN05 0
#endif

// ---------------- scratch (__device__ globals; allocation-free rule) --------
__device__ float g_S [NSQ];
__device__ float g_S2[NSQ];
__device__ float g_S3[NSQ];
__device__ float g_T [NSQ];
__device__ float g_F [NSQ];
__device__ float g_Wf[NSQ];

__device__ __nv_bfloat16 g_sA_hi[NSQ],  g_sA_lo[NSQ];    // S   (A-side, row-major)
__device__ __nv_bfloat16 g_sB_hi[NSQ],  g_sB_lo[NSQ];    // S^T = -S (B-side)
__device__ __nv_bfloat16 g_s2_hi[NSQ],  g_s2_lo[NSQ];    // S2  (A-side)
__device__ __nv_bfloat16 g_s3_hi[NSQ],  g_s3_lo[NSQ];    // S3  (A-side)
__device__ __nv_bfloat16 g_w2t_hi[NSQ], g_w2t_lo[NSQ];   // W2^T (B-side)
__device__ __nv_bfloat16 g_f_hi[NSQ],   g_f_lo[NSQ];     // F   (A-side)
__device__ __nv_bfloat16 g_ft_hi[NSQ],  g_ft_lo[NSQ];    // F^T (B-side)
__device__ __nv_bfloat16 g_wft_hi[NSQ], g_wft_lo[NSQ];   // Wf^T (B-side)
__device__ __nv_bfloat16 g_x_hi[NB*ND], g_x_lo[NB*ND];   // X   (A-side)

// ---------------- common helpers --------------------------------------------
__device__ __forceinline__ void split2(float v, __nv_bfloat16& h, __nv_bfloat16& l) {
    h = __float2bfloat16(v);
    l = __float2bfloat16(v - __bfloat162float(h));
}

#if HAS_TCGEN05
__device__ __forceinline__ uint32_t smem_to_u32(const void* p) {
    uint32_t a;
    asm("{ .reg .u64 t; cvta.to.shared.u64 t, %1; cvt.u32.u64 %0, t; }" : "=r"(a) : "l"(p));
    return a;
}
__device__ __forceinline__ uint32_t elect_one_pred() {
    uint32_t p;
    asm volatile("{\n\t.reg .pred p;\n\telect.sync _|p, 0xFFFFFFFF;\n\t"
                 "selp.b32 %0, 1, 0, p;\n\t}" : "=r"(p));
    return p;
}
#define MBARRIER_INIT(addr, cnt) \
    asm volatile("mbarrier.init.shared.b64 [%0], %1;" :: "r"((uint32_t)(addr)), "r"((uint32_t)(cnt)) : "memory")
#define MBARRIER_INVAL(addr) \
    asm volatile("mbarrier.inval.shared.b64 [%0];" :: "r"((uint32_t)(addr)) : "memory")
#define MBARRIER_WAIT_PARITY(mbar, par) do {                                       \
    uint32_t _m = (uint32_t)(mbar); uint32_t _p = (uint32_t)(par); uint32_t _d;    \
    asm volatile("{\n\t.reg .pred p;\n\t"                                          \
        "mbarrier.try_wait.parity.acquire.cta.shared::cta.b64 p, [%1], %2;\n\t"    \
        "selp.b32 %0, 1, 0, p;\n\t}" : "=r"(_d) : "r"(_m), "r"(_p) : "memory");    \
    if (!_d) {                                                                     \
        asm volatile("{\n\t.reg .pred P1;\n\t"                                     \
        "WL_%=:\n\t"                                                               \
        "mbarrier.try_wait.parity.acquire.cta.shared::cta.b64 P1, [%0], %1, 0x989680;\n\t" \
        "@P1 bra.uni WD_%=;\n\t"                                                   \
        "bra.uni WL_%=;\n\t"                                                       \
        "WD_%=:\n\t}" :: "r"(_m), "r"(_p) : "memory");                             \
    }                                                                              \
} while (0)
#define TCGEN05_ALLOC(sm, n) \
    asm volatile("tcgen05.alloc.cta_group::1.sync.aligned.shared::cta.b32 [%0], %1;" \
                 :: "r"((uint32_t)(sm)), "r"((uint32_t)(n)) : "memory")
#define TCGEN05_DEALLOC(t, n) \
    asm volatile("tcgen05.dealloc.cta_group::1.sync.aligned.b32 %0, %1;" :: "r"(t), "r"((uint32_t)(n)))
#define TCGEN05_RELINQ() \
    asm volatile("tcgen05.relinquish_alloc_permit.cta_group::1.sync.aligned;")
#define TCGEN05_COMMIT(mbar) \
    asm volatile("tcgen05.commit.cta_group::1.mbarrier::arrive::one.shared::cluster.b64 [%0];" \
                 :: "r"((uint32_t)(mbar)) : "memory")
#define TCGEN05_FENCE_AFTER()  asm volatile("tcgen05.fence::after_thread_sync;" ::: "memory")
#define TCGEN05_FENCE_BEFORE() asm volatile("tcgen05.fence::before_thread_sync;" ::: "memory")
#define TCGEN05_WAIT_LD()      asm volatile("tcgen05.wait::ld.sync.aligned;" ::: "memory")
#define FENCE_PROXY_ASYNC()    asm volatile("fence.proxy.async.shared::cta;" ::: "memory")

#define TCGEN05_LD_X32(r, addr) \
    asm volatile("tcgen05.ld.sync.aligned.32x32b.x32.b32 " \
        "{%0, %1, %2, %3, %4, %5, %6, %7, %8, %9, %10, %11, %12, %13, %14, %15, " \
        " %16, %17, %18, %19, %20, %21, %22, %23, %24, %25, %26, %27, %28, %29, %30, %31}, [%32];" \
        : "=r"((r)[0]),  "=r"((r)[1]),  "=r"((r)[2]),  "=r"((r)[3]),  \
          "=r"((r)[4]),  "=r"((r)[5]),  "=r"((r)[6]),  "=r"((r)[7]),  \
          "=r"((r)[8]),  "=r"((r)[9]),  "=r"((r)[10]), "=r"((r)[11]), \
          "=r"((r)[12]), "=r"((r)[13]), "=r"((r)[14]), "=r"((r)[15]), \
          "=r"((r)[16]), "=r"((r)[17]), "=r"((r)[18]), "=r"((r)[19]), \
          "=r"((r)[20]), "=r"((r)[21]), "=r"((r)[22]), "=r"((r)[23]), \
          "=r"((r)[24]), "=r"((r)[25]), "=r"((r)[26]), "=r"((r)[27]), \
          "=r"((r)[28]), "=r"((r)[29]), "=r"((r)[30]), "=r"((r)[31]) \
        : "r"(addr))

// SW128 K-major smem descriptor (layout=2, version=1, SBO=64, LBO=1)
static constexpr u64 DESC_BASE_SW128 =
    (u64(2) << 61) | (u64(1) << 46) | (u64(64) << 32) | (u64(1) << 16);
#define MAKE_DESC(a) (DESC_BASE_SW128 | ((u64)((a) >> 4) & 0x3FFF))

// cg1 bf16 SS MMA: idesc = F32 dtype | BF16 a | BF16 b | (N/8)<<17 | (M/16)<<24
#define MMA_IDESC 0x8200490u   // M=128, N=128
__device__ __forceinline__ void mma_f16_ss(uint32_t d, u64 a, u64 b, uint32_t en) {
    asm volatile("{\n\t.reg .pred p;\n\tsetp.ne.u32 p, %4, 0;\n\t"
        "tcgen05.mma.cta_group::1.kind::f16 [%0], %1, %2, %3, {%5, %5, %5, %5}, p;\n\t}"
        :: "r"(d), "l"(a), "l"(b), "r"(MMA_IDESC), "r"(en), "r"(0u) : "memory");
}
#endif  // HAS_TCGEN05

#define SWZ128(x) ((x) ^ (((x) >> 3) & 0x70))

// ---------------- elementwise kernels ---------------------------------------
__global__ void build_S_kernel(float* __restrict__ S, const float* __restrict__ Sf,
                               __nv_bfloat16* __restrict__ ahi, __nv_bfloat16* __restrict__ alo,
                               __nv_bfloat16* __restrict__ bhi, __nv_bfloat16* __restrict__ blo) {
    int idx = blockIdx.x * blockDim.x + threadIdx.x;
    int r = idx >> 11, c = idx & (ND - 1);
    float v = 0.f;
    if (r != c) {
        int rr = r < c ? r : c, cc = r < c ? c : r;
        int f = rr * (2 * ND - rr - 1) / 2 + (cc - rr - 1);
        v = Sf[f];
        if (r > c) v = -v;
    }
    S[idx] = v;
    __nv_bfloat16 h, l;
    split2(v, h, l);  ahi[idx] = h; alo[idx] = l;
    split2(-v, h, l); bhi[idx] = h; blo[idx] = l;   // S^T = -S
}

// W2^T = I/48 - S/384 + S2/3840 - S3/46080 (bf16 split);  T = S2/8 + S/2 (fp32)
__global__ void ew_prep_kernel(__nv_bfloat16* __restrict__ w2hi, __nv_bfloat16* __restrict__ w2lo,
                               float* __restrict__ T,
                               const float* __restrict__ S, const float* __restrict__ S2,
                               const float* __restrict__ S3) {
    int idx = blockIdx.x * blockDim.x + threadIdx.x;
    int r = idx >> 11, c = idx & (ND - 1);
    float s = S[idx], s2 = S2[idx], s3 = S3[idx];
    float w2t = -s3 * (1.f / 46080.f) + s2 * (1.f / 3840.f) - s * (1.f / 384.f);
    if (r == c) w2t += (1.f / 48.f);
    __nv_bfloat16 h, l;
    split2(w2t, h, l); w2hi[idx] = h; w2lo[idx] = l;
    T[idx] = s2 * 0.125f + s * 0.5f;
}

// 32x32 tiled transpose + bf16 split:  out[c][r] = in[r][c]
__global__ void transpose_conv(const float* __restrict__ in,
                               __nv_bfloat16* __restrict__ thi, __nv_bfloat16* __restrict__ tlo) {
    __shared__ float tile[32][33];
    int bx = blockIdx.x * 32, by = blockIdx.y * 32;
    int tx = threadIdx.x, ty = threadIdx.y;   // 32 x 8
#pragma unroll
    for (int j = 0; j < 4; j++)
        tile[ty + 8 * j][tx] = in[(size_t)(by + ty + 8 * j) * ND + bx + tx];
    __syncthreads();
#pragma unroll
    for (int j = 0; j < 4; j++) {
        float v = tile[tx][ty + 8 * j];
        __nv_bfloat16 h, l; split2(v, h, l);
        size_t o = (size_t)(bx + ty + 8 * j) * ND + by + tx;
        thi[o] = h; tlo[o] = l;
    }
}

// row-major fp32 -> hi/lo bf16 (for X)
__global__ void conv_rm(const float* __restrict__ in,
                        __nv_bfloat16* __restrict__ hi, __nv_bfloat16* __restrict__ lo) {
    int i = blockIdx.x * blockDim.x + threadIdx.x;
    float4 v = ((const float4*)in)[i];
    __nv_bfloat16 h0, l0, h1, l1, h2, l2, h3, l3;
    split2(v.x, h0, l0); split2(v.y, h1, l1); split2(v.z, h2, l2); split2(v.w, h3, l3);
    ((__nv_bfloat162*)hi)[2 * i]     = __nv_bfloat162(h0, h1);
    ((__nv_bfloat162*)hi)[2 * i + 1] = __nv_bfloat162(h2, h3);
    ((__nv_bfloat162*)lo)[2 * i]     = __nv_bfloat162(l0, l1);
    ((__nv_bfloat162*)lo)[2 * i + 1] = __nv_bfloat162(l2, l3);
}

// ---------------- GEMM: C = A @ B^T (+beta*D), A=[M,K] hi/lo, B=[Nn,K] hi/lo -
#define BM 128
#define BN 128
#define BKB 64
#define TBY 16384                       // one 128x64 bf16 sub-tile
#define SM_TILES 1024
#define GEMM_SMEM (SM_TILES + 8 * TBY)  // 132096 bytes

__global__ void __launch_bounds__(256, 1)
gemm_bf3(float* __restrict__ C,
         const __nv_bfloat16* __restrict__ Ahi, const __nv_bfloat16* __restrict__ Alo,
         const __nv_bfloat16* __restrict__ Bhi, const __nv_bfloat16* __restrict__ Blo,
         const float* __restrict__ D, float beta,
         __nv_bfloat16* __restrict__ Chi, __nv_bfloat16* __restrict__ Clo,
         int M, int Nn, int K) {
    extern __shared__ char smem[];
    const int tid = threadIdx.x, wid = tid >> 5, lid = tid & 31;
    const int m0 = blockIdx.y * BM, n0 = blockIdx.x * BN;

#if HAS_TCGEN05
    // ============== tcgen05 split-bf16 path (sm_103a) ==============
    const uint32_t sb = smem_to_u32(smem);
    if (tid == 0) { MBARRIER_INIT(sb + 8, 1); MBARRIER_INIT(sb + 16, 1); }
    if (wid == 0) TCGEN05_ALLOC(sb + 0, 128);
    __syncthreads();
    uint32_t tmem;
    asm volatile("ld.shared.b32 %0, [%1];" : "=r"(tmem) : "r"(sb + 0));

    // per-thread load mapping: 4 chunks of 16B per sub-tile
    int sws[4]; size_t ga[4], gb[4];
#pragma unroll
    for (int j = 0; j < 4; j++) {
        int ch = tid + 256 * j;
        int row = ch >> 3, c16 = ch & 7;
        sws[j] = SWZ128(row * 128 + c16 * 16);
        ga[j] = (size_t)(m0 + row) * K + c16 * 8;
        gb[j] = (size_t)(n0 + row) * K + c16 * 8;
    }

    int ph0 = 0, ph1 = 0;
    const int ktiles = K / BKB;
    for (int t = 0; t < ktiles; t++) {
        const int buf = t & 1;
        if (t >= 2) {
            if (buf == 0) { MBARRIER_WAIT_PARITY(sb + 8, ph0);  ph0 ^= 1; }
            else          { MBARRIER_WAIT_PARITY(sb + 16, ph1); ph1 ^= 1; }
        }
        const int k0 = t * BKB;
        uint4 va[4], vb[4], vc[4], vd[4];
#pragma unroll
        for (int j = 0; j < 4; j++) va[j] = *(const uint4*)(Ahi + ga[j] + k0);
#pragma unroll
        for (int j = 0; j < 4; j++) vb[j] = *(const uint4*)(Alo + ga[j] + k0);
#pragma unroll
        for (int j = 0; j < 4; j++) vc[j] = *(const uint4*)(Bhi + gb[j] + k0);
#pragma unroll
        for (int j = 0; j < 4; j++) vd[j] = *(const uint4*)(Blo + gb[j] + k0);
        char* st = smem + SM_TILES + buf * 4 * TBY;
#pragma unroll
        for (int j = 0; j < 4; j++) *(uint4*)(st + sws[j])           = va[j];
#pragma unroll
        for (int j = 0; j < 4; j++) *(uint4*)(st + TBY + sws[j])     = vb[j];
#pragma unroll
        for (int j = 0; j < 4; j++) *(uint4*)(st + 2 * TBY + sws[j]) = vc[j];
#pragma unroll
        for (int j = 0; j < 4; j++) *(uint4*)(st + 3 * TBY + sws[j]) = vd[j];
        FENCE_PROXY_ASYNC();
        __syncthreads();

        if (wid == 0 && elect_one_pred()) {
            uint32_t base = sb + SM_TILES + buf * 4 * TBY;
            u64 dAh = MAKE_DESC(base);
            u64 dAl = MAKE_DESC(base + TBY);
            u64 dBh = MAKE_DESC(base + 2 * TBY);
            u64 dBl = MAKE_DESC(base + 3 * TBY);
#pragma unroll
            for (int ks = 0; ks < 4; ks++) {
                mma_f16_ss(tmem, dAh + 2 * ks, dBh + 2 * ks, !(t == 0 && ks == 0));
                mma_f16_ss(tmem, dAh + 2 * ks, dBl + 2 * ks, 1u);
                mma_f16_ss(tmem, dAl + 2 * ks, dBh + 2 * ks, 1u);
            }
            TCGEN05_COMMIT(sb + 8 + buf * 8);
        }
    }

    // drain both buffers
    MBARRIER_WAIT_PARITY(sb + 8, ph0);
    MBARRIER_WAIT_PARITY(sb + 16, ph1);
    TCGEN05_FENCE_AFTER();

    if (wid < 4) {
        const int m = m0 + wid * 32 + lid;
#pragma unroll 1
        for (int chk = 0; chk < 4; chk++) {
            uint32_t dreg[32];
            TCGEN05_LD_X32(dreg, tmem + chk * 32);
            TCGEN05_WAIT_LD();
            size_t off = (size_t)m * Nn + n0 + chk * 32;
            float v[32];
#pragma unroll
            for (int i = 0; i < 32; i++) v[i] = __uint_as_float(dreg[i]);
            if (D) {
#pragma unroll
                for (int q = 0; q < 8; q++) {
                    float4 d = *(const float4*)(D + off + 4 * q);
                    v[4 * q + 0] += beta * d.x; v[4 * q + 1] += beta * d.y;
                    v[4 * q + 2] += beta * d.z; v[4 * q + 3] += beta * d.w;
                }
            }
#pragma unroll
            for (int q = 0; q < 8; q++)
                *(float4*)(C + off + 4 * q) =
                    make_float4(v[4 * q], v[4 * q + 1], v[4 * q + 2], v[4 * q + 3]);
            if (Chi) {
#pragma unroll
                for (int p = 0; p < 16; p++) {
                    __nv_bfloat16 h0, l0, h1, l1;
                    split2(v[2 * p], h0, l0); split2(v[2 * p + 1], h1, l1);
                    ((__nv_bfloat162*)(Chi + off))[p] = __nv_bfloat162(h0, h1);
                    ((__nv_bfloat162*)(Clo + off))[p] = __nv_bfloat162(l0, l1);
                }
            }
        }
        TCGEN05_FENCE_BEFORE();
    }

    __syncthreads();
    if (tid == 0) { MBARRIER_INVAL(sb + 8); MBARRIER_INVAL(sb + 16); }
    __syncthreads();
    if (wid == 0) { TCGEN05_RELINQ(); TCGEN05_DEALLOC(tmem, 128); }

#else
    // ============== SIMT fallback (base sm_103 target; correctness net) ======
    // C[m][n] = sum_k (Ahi+Alo)[m][k] * (Bhi+Blo)[n][k]
    float* As = (float*)smem;                    // [16][128]  As[k][m]
    float* Bs = (float*)(smem + 16 * 128 * 4);   // [16][128]  Bs[k][n]

    const int tm = (wid & 3) * 32 + (lid >> 3) * 8;
    const int tn = (wid >> 2) * 64 + (lid & 7) * 8;
    const int trow = tid >> 1;            // 0..127
    const int tk8  = (tid & 1) * 8;       // 0 or 8

    float acc[8][8];
#pragma unroll
    for (int i = 0; i < 8; i++)
#pragma unroll
        for (int j = 0; j < 8; j++) acc[i][j] = 0.f;

    for (int k0 = 0; k0 < K; k0 += 16) {
        // A tile row trow, k-range tk8..tk8+7
        {
            size_t base = (size_t)(m0 + trow) * K + k0 + tk8;
            uint4 h = *(const uint4*)(Ahi + base);
            uint4 l = *(const uint4*)(Alo + base);
            const __nv_bfloat16* hp = (const __nv_bfloat16*)&h;
            const __nv_bfloat16* lp = (const __nv_bfloat16*)&l;
#pragma unroll
            for (int j = 0; j < 8; j++)
                As[(tk8 + j) * 128 + trow] =
                    __bfloat162float(hp[j]) + __bfloat162float(lp[j]);
        }
        {
            size_t base = (size_t)(n0 + trow) * K + k0 + tk8;
            uint4 h = *(const uint4*)(Bhi + base);
            uint4 l = *(const uint4*)(Blo + base);
            const __nv_bfloat16* hp = (const __nv_bfloat16*)&h;
            const __nv_bfloat16* lp = (const __nv_bfloat16*)&l;
#pragma unroll
            for (int j = 0; j < 8; j++)
                Bs[(tk8 + j) * 128 + trow] =
                    __bfloat162float(hp[j]) + __bfloat162float(lp[j]);
        }
        __syncthreads();
#pragma unroll
        for (int kk = 0; kk < 16; kk++) {
            float a[8], b[8];
#pragma unroll
            for (int i = 0; i < 8; i++) a[i] = As[kk * 128 + tm + i];
#pragma unroll
            for (int j = 0; j < 8; j++) b[j] = Bs[kk * 128 + tn + j];
#pragma unroll
            for (int i = 0; i < 8; i++)
#pragma unroll
                for (int j = 0; j < 8; j++) acc[i][j] += a[i] * b[j];
        }
        __syncthreads();
    }

#pragma unroll
    for (int i = 0; i < 8; i++) {
        size_t off = (size_t)(m0 + tm + i) * Nn + n0 + tn;
        float v[8];
#pragma unroll
        for (int j = 0; j < 8; j++) v[j] = acc[i][j];
        if (D) {
#pragma unroll
            for (int j = 0; j < 8; j++) v[j] += beta * D[off + j];
        }
#pragma unroll
        for (int j = 0; j < 8; j++) C[off + j] = v[j];
        if (Chi) {
#pragma unroll
            for (int p = 0; p < 4; p++) {
                __nv_bfloat16 h0, l0, h1, l1;
                split2(v[2 * p], h0, l0); split2(v[2 * p + 1], h1, l1);
                ((__nv_bfloat162*)(Chi + off))[p] = __nv_bfloat162(h0, h1);
                ((__nv_bfloat162*)(Clo + off))[p] = __nv_bfloat162(l0, l1);
            }
        }
    }
#endif
}

// ---------------- launch -----------------------------------------------------
extern "C" void kernel_launch(void* const* d_in, const int* in_sizes, int n_in,
                              void* d_out, int out_size) {
    const float* X  = (const float*)d_in[0];   // [8192, 2048]
    const float* Sf = (const float*)d_in[1];
    float* Y = (float*)d_out;

    cudaFuncSetAttribute(gemm_bf3, cudaFuncAttributeMaxDynamicSharedMemorySize, GEMM_SMEM);

    float *S, *S2, *S3, *T, *F, *Wf;
    cudaGetSymbolAddress((void**)&S, g_S);   cudaGetSymbolAddress((void**)&S2, g_S2);
    cudaGetSymbolAddress((void**)&S3, g_S3); cudaGetSymbolAddress((void**)&T, g_T);
    cudaGetSymbolAddress((void**)&F, g_F);   cudaGetSymbolAddress((void**)&Wf, g_Wf);
    __nv_bfloat16 *sAh, *sAl, *sBh, *sBl, *s2h, *s2l, *s3h, *s3l;
    __nv_bfloat16 *w2h, *w2l, *fh, *fl, *fth, *ftl, *wfh, *wfl, *xh, *xl;
    cudaGetSymbolAddress((void**)&sAh, g_sA_hi);  cudaGetSymbolAddress((void**)&sAl, g_sA_lo);
    cudaGetSymbolAddress((void**)&sBh, g_sB_hi);  cudaGetSymbolAddress((void**)&sBl, g_sB_lo);
    cudaGetSymbolAddress((void**)&s2h, g_s2_hi);  cudaGetSymbolAddress((void**)&s2l, g_s2_lo);
    cudaGetSymbolAddress((void**)&s3h, g_s3_hi);  cudaGetSymbolAddress((void**)&s3l, g_s3_lo);
    cudaGetSymbolAddress((void**)&w2h, g_w2t_hi); cudaGetSymbolAddress((void**)&w2l, g_w2t_lo);
    cudaGetSymbolAddress((void**)&fh, g_f_hi);    cudaGetSymbolAddress((void**)&fl, g_f_lo);
    cudaGetSymbolAddress((void**)&fth, g_ft_hi);  cudaGetSymbolAddress((void**)&ftl, g_ft_lo);
    cudaGetSymbolAddress((void**)&wfh, g_wft_hi); cudaGetSymbolAddress((void**)&wfl, g_wft_lo);
    cudaGetSymbolAddress((void**)&xh, g_x_hi);    cudaGetSymbolAddress((void**)&xl, g_x_lo);

    const int EW_BLOCKS = NSQ / 256;
    build_S_kernel<<<EW_BLOCKS, 256>>>(S, Sf, sAh, sAl, sBh, sBl);

    dim3 gSq(ND / BN, ND / BM);
    // S2 = S @ S
    gemm_bf3<<<gSq, 256, GEMM_SMEM>>>(S2, sAh, sAl, sBh, sBl, nullptr, 0.f, s2h, s2l, ND, ND, ND);
    // S3 = S2 @ S
    gemm_bf3<<<gSq, 256, GEMM_SMEM>>>(S3, s2h, s2l, sBh, sBl, nullptr, 0.f, s3h, s3l, ND, ND, ND);
    // W2^T (bf16) and T = Finit
    ew_prep_kernel<<<EW_BLOCKS, 256>>>(w2h, w2l, T, S, S2, S3);
    // F = S3 @ W2 + T
    gemm_bf3<<<gSq, 256, GEMM_SMEM>>>(F, s3h, s3l, w2h, w2l, T, 1.f, fh, fl, ND, ND, ND);
    // F^T bf16
    dim3 gT(ND / 32, ND / 32), bT(32, 8);
    transpose_conv<<<gT, bT>>>(F, fth, ftl);
    // Wf = F @ F + 2F
    gemm_bf3<<<gSq, 256, GEMM_SMEM>>>(Wf, fh, fl, fth, ftl, F, 2.f, nullptr, nullptr, ND, ND, ND);
    // Wf^T bf16
    transpose_conv<<<gT, bT>>>(Wf, wfh, wfl);
    // X -> hi/lo bf16
    conv_rm<<<(NB * ND / 4) / 256, 256>>>(X, xh, xl);
    // Y = X @ Wf + X
    dim3 gX(ND / BN, NB / BM);
    gemm_bf3<<<gX, 256, GEMM_SMEM>>>(Y, xh, xl, wfh, wfl, X, 1.f, nullptr, nullptr, NB, ND, ND);
}

// round 7
// speedup vs baseline: 5.7366x; 1.5049x over previous
#include <cuda_runtime.h>
#include <cuda_bf16.h>
#include <cstdint>

typedef unsigned long long u64;

#define ND 2048
#define NB 8192
#define NSQ (ND*ND)

// tcgen05 is arch-SPECIFIC (sm_103a pass only); base compute_103 pass gets a
// SIMT fallback body so ptxas never sees tcgen05 on the base target.
#if defined(__CUDA_ARCH__) && (defined(__CUDA_ARCH_FEAT_SM103_ALL) || defined(__CUDA_ARCH_FEAT_SM100_ALL) || defined(__CUDA_ARCH_FEAT_SM101_ALL))
#define HAS_TCGEN05 1
#else
#define HAS_TCGEN05 0
#endif

// ---------------- scratch (__device__ globals; allocation-free rule) --------
__device__ float g_S [NSQ];
__device__ float g_S2[NSQ];
__device__ float g_S3[NSQ];
__device__ float g_T [NSQ];
__device__ float g_F [NSQ];
__device__ float g_Wf[NSQ];

__device__ __nv_bfloat16 g_sA_hi[NSQ],  g_sA_lo[NSQ];    // S   (A-side)
__device__ __nv_bfloat16 g_sB_hi[NSQ],  g_sB_lo[NSQ];    // S^T = -S (B-side)
__device__ __nv_bfloat16 g_s2_hi[NSQ],  g_s2_lo[NSQ];    // S2  (A-side)
__device__ __nv_bfloat16 g_s3_hi[NSQ],  g_s3_lo[NSQ];    // S3  (A-side)
__device__ __nv_bfloat16 g_w2t_hi[NSQ], g_w2t_lo[NSQ];   // W2^T (B-side)
__device__ __nv_bfloat16 g_f_hi[NSQ],   g_f_lo[NSQ];     // F   (A-side)
__device__ __nv_bfloat16 g_ft_hi[NSQ],  g_ft_lo[NSQ];    // F^T (B-side)
__device__ __nv_bfloat16 g_wft_hi[NSQ], g_wft_lo[NSQ];   // (Wf+I)^T (B-side)
__device__ __nv_bfloat16 g_x_hi[NB*ND], g_x_lo[NB*ND];   // X   (A-side)

// ---------------- common helpers --------------------------------------------
__device__ __forceinline__ void split2(float v, __nv_bfloat16& h, __nv_bfloat16& l) {
    h = __float2bfloat16(v);
    l = __float2bfloat16(v - __bfloat162float(h));
}

#define SWZ128(x) ((x) ^ (((x) >> 3) & 0x70))

#if HAS_TCGEN05
__device__ __forceinline__ uint32_t smem_to_u32(const void* p) {
    uint32_t a;
    asm("{ .reg .u64 t; cvta.to.shared.u64 t, %1; cvt.u32.u64 %0, t; }" : "=r"(a) : "l"(p));
    return a;
}
__device__ __forceinline__ uint32_t elect_one_pred() {
    uint32_t p;
    asm volatile("{\n\t.reg .pred p;\n\telect.sync _|p, 0xFFFFFFFF;\n\t"
                 "selp.b32 %0, 1, 0, p;\n\t}" : "=r"(p));
    return p;
}
#define MBARRIER_INIT(addr, cnt) \
    asm volatile("mbarrier.init.shared.b64 [%0], %1;" :: "r"((uint32_t)(addr)), "r"((uint32_t)(cnt)) : "memory")
#define MBARRIER_INVAL(addr) \
    asm volatile("mbarrier.inval.shared.b64 [%0];" :: "r"((uint32_t)(addr)) : "memory")
#define MBARRIER_WAIT_PARITY(mbar, par) do {                                       \
    uint32_t _m = (uint32_t)(mbar); uint32_t _p = (uint32_t)(par); uint32_t _d;    \
    asm volatile("{\n\t.reg .pred p;\n\t"                                          \
        "mbarrier.try_wait.parity.acquire.cta.shared::cta.b64 p, [%1], %2;\n\t"    \
        "selp.b32 %0, 1, 0, p;\n\t}" : "=r"(_d) : "r"(_m), "r"(_p) : "memory");    \
    if (!_d) {                                                                     \
        asm volatile("{\n\t.reg .pred P1;\n\t"                                     \
        "WL_%=:\n\t"                                                               \
        "mbarrier.try_wait.parity.acquire.cta.shared::cta.b64 P1, [%0], %1, 0x989680;\n\t" \
        "@P1 bra.uni WD_%=;\n\t"                                                   \
        "bra.uni WL_%=;\n\t"                                                       \
        "WD_%=:\n\t}" :: "r"(_m), "r"(_p) : "memory");                             \
    }                                                                              \
} while (0)
#define TCGEN05_ALLOC(sm, n) \
    asm volatile("tcgen05.alloc.cta_group::1.sync.aligned.shared::cta.b32 [%0], %1;" \
                 :: "r"((uint32_t)(sm)), "r"((uint32_t)(n)) : "memory")
#define TCGEN05_DEALLOC(t, n) \
    asm volatile("tcgen05.dealloc.cta_group::1.sync.aligned.b32 %0, %1;" :: "r"(t), "r"((uint32_t)(n)))
#define TCGEN05_RELINQ() \
    asm volatile("tcgen05.relinquish_alloc_permit.cta_group::1.sync.aligned;")
#define TCGEN05_COMMIT(mbar) \
    asm volatile("tcgen05.commit.cta_group::1.mbarrier::arrive::one.shared::cluster.b64 [%0];" \
                 :: "r"((uint32_t)(mbar)) : "memory")
#define TCGEN05_FENCE_AFTER()  asm volatile("tcgen05.fence::after_thread_sync;" ::: "memory")
#define TCGEN05_FENCE_BEFORE() asm volatile("tcgen05.fence::before_thread_sync;" ::: "memory")
#define TCGEN05_WAIT_LD()      asm volatile("tcgen05.wait::ld.sync.aligned;" ::: "memory")
#define FENCE_PROXY_ASYNC()    asm volatile("fence.proxy.async.shared::cta;" ::: "memory")
#define CP_ASYNC16(dst, src) \
    asm volatile("cp.async.cg.shared.global [%0], [%1], 16;" :: "r"((uint32_t)(dst)), "l"(src) : "memory")
#define CP_ASYNC_COMMIT() asm volatile("cp.async.commit_group;" ::: "memory")
#define CP_ASYNC_WAIT0()  asm volatile("cp.async.wait_group 0;" ::: "memory")

#define TCGEN05_LD_X32(r, addr) \
    asm volatile("tcgen05.ld.sync.aligned.32x32b.x32.b32 " \
        "{%0, %1, %2, %3, %4, %5, %6, %7, %8, %9, %10, %11, %12, %13, %14, %15, " \
        " %16, %17, %18, %19, %20, %21, %22, %23, %24, %25, %26, %27, %28, %29, %30, %31}, [%32];" \
        : "=r"((r)[0]),  "=r"((r)[1]),  "=r"((r)[2]),  "=r"((r)[3]),  \
          "=r"((r)[4]),  "=r"((r)[5]),  "=r"((r)[6]),  "=r"((r)[7]),  \
          "=r"((r)[8]),  "=r"((r)[9]),  "=r"((r)[10]), "=r"((r)[11]), \
          "=r"((r)[12]), "=r"((r)[13]), "=r"((r)[14]), "=r"((r)[15]), \
          "=r"((r)[16]), "=r"((r)[17]), "=r"((r)[18]), "=r"((r)[19]), \
          "=r"((r)[20]), "=r"((r)[21]), "=r"((r)[22]), "=r"((r)[23]), \
          "=r"((r)[24]), "=r"((r)[25]), "=r"((r)[26]), "=r"((r)[27]), \
          "=r"((r)[28]), "=r"((r)[29]), "=r"((r)[30]), "=r"((r)[31]) \
        : "r"(addr))

// SW128 K-major smem descriptor (layout=2, version=1, SBO=64, LBO=1)
static constexpr u64 DESC_BASE_SW128 =
    (u64(2) << 61) | (u64(1) << 46) | (u64(64) << 32) | (u64(1) << 16);
#define MAKE_DESC(a) (DESC_BASE_SW128 | ((u64)((a) >> 4) & 0x3FFF))

// cg1 bf16 SS MMA: idesc = F32 | BF16 a | BF16 b | (N/8)<<17 | (M/16)<<24
#define MMA_IDESC 0x8400490u   // M=128, N=256
__device__ __forceinline__ void mma_f16_ss(uint32_t d, u64 a, u64 b, uint32_t en) {
    asm volatile("{\n\t.reg .pred p;\n\tsetp.ne.u32 p, %4, 0;\n\t"
        "tcgen05.mma.cta_group::1.kind::f16 [%0], %1, %2, %3, {%5, %5, %5, %5}, p;\n\t}"
        :: "r"(d), "l"(a), "l"(b), "r"(MMA_IDESC), "r"(en), "r"(0u) : "memory");
}
#endif  // HAS_TCGEN05

// ---------------- elementwise kernels ---------------------------------------
__global__ void build_S_kernel(float* __restrict__ S, const float* __restrict__ Sf,
                               __nv_bfloat16* __restrict__ ahi, __nv_bfloat16* __restrict__ alo,
                               __nv_bfloat16* __restrict__ bhi, __nv_bfloat16* __restrict__ blo) {
    int idx = blockIdx.x * blockDim.x + threadIdx.x;
    int r = idx >> 11, c = idx & (ND - 1);
    float v = 0.f;
    if (r != c) {
        int rr = r < c ? r : c, cc = r < c ? c : r;
        int f = rr * (2 * ND - rr - 1) / 2 + (cc - rr - 1);
        v = Sf[f];
        if (r > c) v = -v;
    }
    S[idx] = v;
    __nv_bfloat16 h, l;
    split2(v, h, l);  ahi[idx] = h; alo[idx] = l;
    split2(-v, h, l); bhi[idx] = h; blo[idx] = l;   // S^T = -S
}

// W2^T = I/48 - S/384 + S2/3840 - S3/46080 (bf16 split);  T = S2/8 + S/2 (fp32)
__global__ void ew_prep_kernel(__nv_bfloat16* __restrict__ w2hi, __nv_bfloat16* __restrict__ w2lo,
                               float* __restrict__ T,
                               const float* __restrict__ S, const float* __restrict__ S2,
                               const float* __restrict__ S3) {
    int idx = blockIdx.x * blockDim.x + threadIdx.x;
    int r = idx >> 11, c = idx & (ND - 1);
    float s = S[idx], s2 = S2[idx], s3 = S3[idx];
    float w2t = -s3 * (1.f / 46080.f) + s2 * (1.f / 3840.f) - s * (1.f / 384.f);
    if (r == c) w2t += (1.f / 48.f);
    __nv_bfloat16 h, l;
    split2(w2t, h, l); w2hi[idx] = h; w2lo[idx] = l;
    T[idx] = s2 * 0.125f + s * 0.5f;
}

// 32x32 tiled transpose + optional diagonal add + bf16 split
__global__ void transpose_conv(const float* __restrict__ in,
                               __nv_bfloat16* __restrict__ thi, __nv_bfloat16* __restrict__ tlo,
                               float idadd) {
    __shared__ float tile[32][33];
    int bx = blockIdx.x * 32, by = blockIdx.y * 32;
    int tx = threadIdx.x, ty = threadIdx.y;   // 32 x 8
#pragma unroll
    for (int j = 0; j < 4; j++)
        tile[ty + 8 * j][tx] = in[(size_t)(by + ty + 8 * j) * ND + bx + tx];
    __syncthreads();
#pragma unroll
    for (int j = 0; j < 4; j++) {
        int ro = bx + ty + 8 * j, co = by + tx;
        float v = tile[tx][ty + 8 * j];
        if (ro == co) v += idadd;
        __nv_bfloat16 h, l; split2(v, h, l);
        size_t o = (size_t)ro * ND + co;
        thi[o] = h; tlo[o] = l;
    }
}

// row-major fp32 -> hi/lo bf16 (for X)
__global__ void conv_rm(const float* __restrict__ in,
                        __nv_bfloat16* __restrict__ hi, __nv_bfloat16* __restrict__ lo) {
    int i = blockIdx.x * blockDim.x + threadIdx.x;
    float4 v = ((const float4*)in)[i];
    __nv_bfloat16 h0, l0, h1, l1, h2, l2, h3, l3;
    split2(v.x, h0, l0); split2(v.y, h1, l1); split2(v.z, h2, l2); split2(v.w, h3, l3);
    ((__nv_bfloat162*)hi)[2 * i]     = __nv_bfloat162(h0, h1);
    ((__nv_bfloat162*)hi)[2 * i + 1] = __nv_bfloat162(h2, h3);
    ((__nv_bfloat162*)lo)[2 * i]     = __nv_bfloat162(l0, l1);
    ((__nv_bfloat162*)lo)[2 * i + 1] = __nv_bfloat162(l2, l3);
}

// ---------------- GEMM: C = A @ B^T (+beta*D), A=[M,K] hi/lo, B=[Nn,K] hi/lo -
// 128x256 tile, BK=64, cp.async loads, double-buffered, tcgen05 kind::f16.
#define BM 128
#define BN 256
#define BKB 64
#define A_SUB 16384                    // 128x64 bf16
#define B_SUB 32768                    // 256x64 bf16
#define STAGE_BY (2 * A_SUB + 2 * B_SUB)   // 98304
#define SM_HDR 1024
#define GEMM_SMEM (SM_HDR + 2 * STAGE_BY)  // 197632 bytes

__global__ void __launch_bounds__(256, 1)
gemm_bf3(float* __restrict__ C,
         const __nv_bfloat16* __restrict__ Ahi, const __nv_bfloat16* __restrict__ Alo,
         const __nv_bfloat16* __restrict__ Bhi, const __nv_bfloat16* __restrict__ Blo,
         const float* __restrict__ D, float beta,
         __nv_bfloat16* __restrict__ Chi, __nv_bfloat16* __restrict__ Clo,
         int M, int Nn, int K) {
    extern __shared__ char smem[];
    const int tid = threadIdx.x, wid = tid >> 5, lid = tid & 31;
    const int m0 = blockIdx.y * BM, n0 = blockIdx.x * BN;

#if HAS_TCGEN05
    const uint32_t sb = smem_to_u32(smem);
    if (tid == 0) { MBARRIER_INIT(sb + 8, 1); MBARRIER_INIT(sb + 16, 1); }
    if (wid == 0) TCGEN05_ALLOC(sb + 0, 256);
    __syncthreads();
    uint32_t tmem;
    asm volatile("ld.shared.b32 %0, [%1];" : "=r"(tmem) : "r"(sb + 0));

    // cp.async mappings: A subtile 1024 chunks (4/thread), B subtile 2048 (8/thread)
    int aswz[4]; size_t goa[4];
#pragma unroll
    for (int j = 0; j < 4; j++) {
        int ch = tid + 256 * j;
        int row = ch >> 3, c16 = ch & 7;
        aswz[j] = SWZ128(row * 128 + c16 * 16);
        goa[j] = (size_t)(m0 + row) * K + c16 * 8;
    }
    int bswz[8]; size_t gob[8];
#pragma unroll
    for (int j = 0; j < 8; j++) {
        int ch = tid + 256 * j;
        int row = ch >> 3, c16 = ch & 7;
        bswz[j] = SWZ128(row * 128 + c16 * 16);
        gob[j] = (size_t)(n0 + row) * K + c16 * 8;
    }

    int ph0 = 0, ph1 = 0;
    const int ktiles = K / BKB;
    for (int t = 0; t < ktiles; t++) {
        const int buf = t & 1;
        if (t >= 2) {
            if (buf == 0) { MBARRIER_WAIT_PARITY(sb + 8, ph0);  ph0 ^= 1; }
            else          { MBARRIER_WAIT_PARITY(sb + 16, ph1); ph1 ^= 1; }
        }
        const int k0 = t * BKB;
        const uint32_t st = sb + SM_HDR + buf * STAGE_BY;
#pragma unroll
        for (int j = 0; j < 4; j++) CP_ASYNC16(st + aswz[j],          Ahi + goa[j] + k0);
#pragma unroll
        for (int j = 0; j < 4; j++) CP_ASYNC16(st + A_SUB + aswz[j],  Alo + goa[j] + k0);
#pragma unroll
        for (int j = 0; j < 8; j++) CP_ASYNC16(st + 2*A_SUB + bswz[j],        Bhi + gob[j] + k0);
#pragma unroll
        for (int j = 0; j < 8; j++) CP_ASYNC16(st + 2*A_SUB + B_SUB + bswz[j], Blo + gob[j] + k0);
        CP_ASYNC_COMMIT();
        CP_ASYNC_WAIT0();
        FENCE_PROXY_ASYNC();
        __syncthreads();

        if (wid == 0 && elect_one_pred()) {
            u64 dAh = MAKE_DESC(st);
            u64 dAl = MAKE_DESC(st + A_SUB);
            u64 dBh = MAKE_DESC(st + 2 * A_SUB);
            u64 dBl = MAKE_DESC(st + 2 * A_SUB + B_SUB);
#pragma unroll
            for (int ks = 0; ks < 4; ks++) {
                mma_f16_ss(tmem, dAh + 2 * ks, dBh + 2 * ks, !(t == 0 && ks == 0));
                mma_f16_ss(tmem, dAh + 2 * ks, dBl + 2 * ks, 1u);
                mma_f16_ss(tmem, dAl + 2 * ks, dBh + 2 * ks, 1u);
            }
            TCGEN05_COMMIT(sb + 8 + buf * 8);
        }
    }

    MBARRIER_WAIT_PARITY(sb + 8, ph0);
    MBARRIER_WAIT_PARITY(sb + 16, ph1);
    TCGEN05_FENCE_AFTER();

    if (wid < 4) {
        const int m = m0 + wid * 32 + lid;
#pragma unroll 1
        for (int chk = 0; chk < 8; chk++) {
            uint32_t dreg[32];
            TCGEN05_LD_X32(dreg, tmem + chk * 32);
            TCGEN05_WAIT_LD();
            size_t off = (size_t)m * Nn + n0 + chk * 32;
            float v[32];
#pragma unroll
            for (int i = 0; i < 32; i++) v[i] = __uint_as_float(dreg[i]);
            if (D) {
#pragma unroll
                for (int q = 0; q < 8; q++) {
                    float4 d = *(const float4*)(D + off + 4 * q);
                    v[4 * q + 0] += beta * d.x; v[4 * q + 1] += beta * d.y;
                    v[4 * q + 2] += beta * d.z; v[4 * q + 3] += beta * d.w;
                }
            }
#pragma unroll
            for (int q = 0; q < 8; q++)
                *(float4*)(C + off + 4 * q) =
                    make_float4(v[4 * q], v[4 * q + 1], v[4 * q + 2], v[4 * q + 3]);
            if (Chi) {
#pragma unroll
                for (int p = 0; p < 16; p++) {
                    __nv_bfloat16 h0, l0, h1, l1;
                    split2(v[2 * p], h0, l0); split2(v[2 * p + 1], h1, l1);
                    ((__nv_bfloat162*)(Chi + off))[p] = __nv_bfloat162(h0, h1);
                    ((__nv_bfloat162*)(Clo + off))[p] = __nv_bfloat162(l0, l1);
                }
            }
        }
        TCGEN05_FENCE_BEFORE();
    }

    __syncthreads();
    if (tid == 0) { MBARRIER_INVAL(sb + 8); MBARRIER_INVAL(sb + 16); }
    __syncthreads();
    if (wid == 0) { TCGEN05_RELINQ(); TCGEN05_DEALLOC(tmem, 256); }

#else
    // ============== SIMT fallback (base sm_103 target; never runs on GB300) ==
    float* As = (float*)smem;                    // [16][128]  As[k][m]
    float* Bs = (float*)(smem + 16 * 128 * 4);   // [16][128]  Bs[k][n]
    const int tm = (wid & 3) * 32 + (lid >> 3) * 8;
    const int tn_ = (wid >> 2) * 64 + (lid & 7) * 8;
    const int trow = tid >> 1;
    const int tk8  = (tid & 1) * 8;

    for (int h = 0; h < 2; h++) {
        const int n0h = n0 + 128 * h;
        float acc[8][8];
#pragma unroll
        for (int i = 0; i < 8; i++)
#pragma unroll
            for (int j = 0; j < 8; j++) acc[i][j] = 0.f;
        for (int k0 = 0; k0 < K; k0 += 16) {
            {
                size_t base = (size_t)(m0 + trow) * K + k0 + tk8;
                uint4 hh = *(const uint4*)(Ahi + base);
                uint4 ll = *(const uint4*)(Alo + base);
                const __nv_bfloat16* hp = (const __nv_bfloat16*)&hh;
                const __nv_bfloat16* lp = (const __nv_bfloat16*)&ll;
#pragma unroll
                for (int j = 0; j < 8; j++)
                    As[(tk8 + j) * 128 + trow] = __bfloat162float(hp[j]) + __bfloat162float(lp[j]);
            }
            {
                size_t base = (size_t)(n0h + trow) * K + k0 + tk8;
                uint4 hh = *(const uint4*)(Bhi + base);
                uint4 ll = *(const uint4*)(Blo + base);
                const __nv_bfloat16* hp = (const __nv_bfloat16*)&hh;
                const __nv_bfloat16* lp = (const __nv_bfloat16*)&ll;
#pragma unroll
                for (int j = 0; j < 8; j++)
                    Bs[(tk8 + j) * 128 + trow] = __bfloat162float(hp[j]) + __bfloat162float(lp[j]);
            }
            __syncthreads();
#pragma unroll
            for (int kk = 0; kk < 16; kk++) {
                float a[8], b[8];
#pragma unroll
                for (int i = 0; i < 8; i++) a[i] = As[kk * 128 + tm + i];
#pragma unroll
                for (int j = 0; j < 8; j++) b[j] = Bs[kk * 128 + tn_ + j];
#pragma unroll
                for (int i = 0; i < 8; i++)
#pragma unroll
                    for (int j = 0; j < 8; j++) acc[i][j] += a[i] * b[j];
            }
            __syncthreads();
        }
#pragma unroll
        for (int i = 0; i < 8; i++) {
            size_t off = (size_t)(m0 + tm + i) * Nn + n0h + tn_;
            float v[8];
#pragma unroll
            for (int j = 0; j < 8; j++) v[j] = acc[i][j];
            if (D) {
#pragma unroll
                for (int j = 0; j < 8; j++) v[j] += beta * D[off + j];
            }
#pragma unroll
            for (int j = 0; j < 8; j++) C[off + j] = v[j];
            if (Chi) {
#pragma unroll
                for (int p = 0; p < 4; p++) {
                    __nv_bfloat16 h0, l0, h1, l1;
                    split2(v[2 * p], h0, l0); split2(v[2 * p + 1], h1, l1);
                    ((__nv_bfloat162*)(Chi + off))[p] = __nv_bfloat162(h0, h1);
                    ((__nv_bfloat162*)(Clo + off))[p] = __nv_bfloat162(l0, l1);
                }
            }
        }
        __syncthreads();
    }
#endif
}

// ---------------- launch -----------------------------------------------------
extern "C" void kernel_launch(void* const* d_in, const int* in_sizes, int n_in,
                              void* d_out, int out_size) {
    const float* X  = (const float*)d_in[0];   // [8192, 2048]
    const float* Sf = (const float*)d_in[1];
    float* Y = (float*)d_out;

    cudaFuncSetAttribute(gemm_bf3, cudaFuncAttributeMaxDynamicSharedMemorySize, GEMM_SMEM);

    float *S, *S2, *S3, *T, *F, *Wf;
    cudaGetSymbolAddress((void**)&S, g_S);   cudaGetSymbolAddress((void**)&S2, g_S2);
    cudaGetSymbolAddress((void**)&S3, g_S3); cudaGetSymbolAddress((void**)&T, g_T);
    cudaGetSymbolAddress((void**)&F, g_F);   cudaGetSymbolAddress((void**)&Wf, g_Wf);
    __nv_bfloat16 *sAh, *sAl, *sBh, *sBl, *s2h, *s2l, *s3h, *s3l;
    __nv_bfloat16 *w2h, *w2l, *fh, *fl, *fth, *ftl, *wfh, *wfl, *xh, *xl;
    cudaGetSymbolAddress((void**)&sAh, g_sA_hi);  cudaGetSymbolAddress((void**)&sAl, g_sA_lo);
    cudaGetSymbolAddress((void**)&sBh, g_sB_hi);  cudaGetSymbolAddress((void**)&sBl, g_sB_lo);
    cudaGetSymbolAddress((void**)&s2h, g_s2_hi);  cudaGetSymbolAddress((void**)&s2l, g_s2_lo);
    cudaGetSymbolAddress((void**)&s3h, g_s3_hi);  cudaGetSymbolAddress((void**)&s3l, g_s3_lo);
    cudaGetSymbolAddress((void**)&w2h, g_w2t_hi); cudaGetSymbolAddress((void**)&w2l, g_w2t_lo);
    cudaGetSymbolAddress((void**)&fh, g_f_hi);    cudaGetSymbolAddress((void**)&fl, g_f_lo);
    cudaGetSymbolAddress((void**)&fth, g_ft_hi);  cudaGetSymbolAddress((void**)&ftl, g_ft_lo);
    cudaGetSymbolAddress((void**)&wfh, g_wft_hi); cudaGetSymbolAddress((void**)&wfl, g_wft_lo);
    cudaGetSymbolAddress((void**)&xh, g_x_hi);    cudaGetSymbolAddress((void**)&xl, g_x_lo);

    const int EW_BLOCKS = NSQ / 256;
    build_S_kernel<<<EW_BLOCKS, 256>>>(S, Sf, sAh, sAl, sBh, sBl);

    dim3 gSq(ND / BN, ND / BM);     // (8, 16)
    // S2 = S @ S
    gemm_bf3<<<gSq, 256, GEMM_SMEM>>>(S2, sAh, sAl, sBh, sBl, nullptr, 0.f, s2h, s2l, ND, ND, ND);
    // S3 = S2 @ S
    gemm_bf3<<<gSq, 256, GEMM_SMEM>>>(S3, s2h, s2l, sBh, sBl, nullptr, 0.f, s3h, s3l, ND, ND, ND);
    // W2^T (bf16) and T = Finit
    ew_prep_kernel<<<EW_BLOCKS, 256>>>(w2h, w2l, T, S, S2, S3);
    // F = S3 @ W2 + T
    gemm_bf3<<<gSq, 256, GEMM_SMEM>>>(F, s3h, s3l, w2h, w2l, T, 1.f, fh, fl, ND, ND, ND);
    // F^T bf16
    dim3 gT(ND / 32, ND / 32), bT(32, 8);
    transpose_conv<<<gT, bT>>>(F, fth, ftl, 0.f);
    // Wf = F @ F + 2F
    gemm_bf3<<<gSq, 256, GEMM_SMEM>>>(Wf, fh, fl, fth, ftl, F, 2.f, nullptr, nullptr, ND, ND, ND);
    // (Wf + I)^T bf16  (identity folded in -> big GEMM needs no D term)
    transpose_conv<<<gT, bT>>>(Wf, wfh, wfl, 1.f);
    // X -> hi/lo bf16
    conv_rm<<<(NB * ND / 4) / 256, 256>>>(X, xh, xl);
    // Y = X @ (Wf + I)
    dim3 gX(ND / BN, NB / BM);      // (8, 64)
    gemm_bf3<<<gX, 256, GEMM_SMEM>>>(Y, xh, xl, wfh, wfl, nullptr, 0.f, nullptr, nullptr, NB, ND, ND);
}

// round 9
// speedup vs baseline: 5.8472x; 1.0193x over previous
#include <cuda_runtime.h>
#include <cuda_bf16.h>
#include <cstdint>

typedef unsigned long long u64;

#define ND 2048
#define NB 8192
#define NSQ (ND*ND)

// tcgen05 is arch-SPECIFIC (sm_103a pass only); base compute_103 pass gets a
// SIMT fallback body so ptxas never sees tcgen05 on the base target.
#if defined(__CUDA_ARCH__) && (defined(__CUDA_ARCH_FEAT_SM103_ALL) || defined(__CUDA_ARCH_FEAT_SM100_ALL) || defined(__CUDA_ARCH_FEAT_SM101_ALL))
#define HAS_TCGEN05 1
#else
#define HAS_TCGEN05 0
#endif

// ---------------- scratch (__device__ globals; allocation-free rule) --------
__device__ float g_S [NSQ];
__device__ float g_S2[NSQ];
__device__ float g_S3[NSQ];
__device__ float g_T [NSQ];
__device__ float g_F [NSQ];
__device__ float g_Wf[NSQ];

__device__ __nv_bfloat16 g_sA_hi[NSQ],  g_sA_lo[NSQ];    // S   (A-side)
__device__ __nv_bfloat16 g_sB_hi[NSQ],  g_sB_lo[NSQ];    // S^T = -S (B-side)
__device__ __nv_bfloat16 g_s2_hi[NSQ],  g_s2_lo[NSQ];    // S2  (A-side)
__device__ __nv_bfloat16 g_s3_hi[NSQ],  g_s3_lo[NSQ];    // S3  (A-side)
__device__ __nv_bfloat16 g_w2t_hi[NSQ], g_w2t_lo[NSQ];   // W2^T (B-side)
__device__ __nv_bfloat16 g_f_hi[NSQ],   g_f_lo[NSQ];     // F   (A-side)
__device__ __nv_bfloat16 g_ft_hi[NSQ],  g_ft_lo[NSQ];    // F^T (B-side)
__device__ __nv_bfloat16 g_wft_hi[NSQ], g_wft_lo[NSQ];   // (Wf+I)^T (B-side)
__device__ __nv_bfloat16 g_x_hi[NB*ND], g_x_lo[NB*ND];   // X   (A-side)

// ---------------- common helpers --------------------------------------------
__device__ __forceinline__ void split2(float v, __nv_bfloat16& h, __nv_bfloat16& l) {
    h = __float2bfloat16(v);
    l = __float2bfloat16(v - __bfloat162float(h));
}

#define SWZ128(x) ((x) ^ (((x) >> 3) & 0x70))

#if HAS_TCGEN05
__device__ __forceinline__ uint32_t smem_to_u32(const void* p) {
    uint32_t a;
    asm("{ .reg .u64 t; cvta.to.shared.u64 t, %1; cvt.u32.u64 %0, t; }" : "=r"(a) : "l"(p));
    return a;
}
__device__ __forceinline__ uint32_t elect_one_pred() {
    uint32_t p;
    asm volatile("{\n\t.reg .pred p;\n\telect.sync _|p, 0xFFFFFFFF;\n\t"
                 "selp.b32 %0, 1, 0, p;\n\t}" : "=r"(p));
    return p;
}
#define MBARRIER_INIT(addr, cnt) \
    asm volatile("mbarrier.init.shared.b64 [%0], %1;" :: "r"((uint32_t)(addr)), "r"((uint32_t)(cnt)) : "memory")
#define MBARRIER_INVAL(addr) \
    asm volatile("mbarrier.inval.shared.b64 [%0];" :: "r"((uint32_t)(addr)) : "memory")
#define MBARRIER_WAIT_PARITY(mbar, par) do {                                       \
    uint32_t _m = (uint32_t)(mbar); uint32_t _p = (uint32_t)(par); uint32_t _d;    \
    asm volatile("{\n\t.reg .pred p;\n\t"                                          \
        "mbarrier.try_wait.parity.acquire.cta.shared::cta.b64 p, [%1], %2;\n\t"    \
        "selp.b32 %0, 1, 0, p;\n\t}" : "=r"(_d) : "r"(_m), "r"(_p) : "memory");    \
    if (!_d) {                                                                     \
        asm volatile("{\n\t.reg .pred P1;\n\t"                                     \
        "WL_%=:\n\t"                                                               \
        "mbarrier.try_wait.parity.acquire.cta.shared::cta.b64 P1, [%0], %1, 0x989680;\n\t" \
        "@P1 bra.uni WD_%=;\n\t"                                                   \
        "bra.uni WL_%=;\n\t"                                                       \
        "WD_%=:\n\t}" :: "r"(_m), "r"(_p) : "memory");                             \
    }                                                                              \
} while (0)
// arrive on the same-offset mbarrier in cluster rank 0 (leader)
#define MBAR_ARRIVE_LEADER(localaddr) \
    asm volatile("{\n\t.reg .b32 ra;\n\t" \
        "mapa.shared::cluster.u32 ra, %0, 0;\n\t" \
        "mbarrier.arrive.shared::cluster.b64 _, [ra];\n\t}" \
        :: "r"((uint32_t)(localaddr)) : "memory")
#define CLUSTER_SYNC() do { \
    asm volatile("barrier.cluster.arrive.aligned;" ::: "memory"); \
    asm volatile("barrier.cluster.wait.aligned;" ::: "memory"); \
} while (0)
#define TCGEN05_ALLOC_CG2(sm, n) \
    asm volatile("tcgen05.alloc.cta_group::2.sync.aligned.shared::cta.b32 [%0], %1;" \
                 :: "r"((uint32_t)(sm)), "r"((uint32_t)(n)) : "memory")
#define TCGEN05_DEALLOC_CG2(t, n) \
    asm volatile("tcgen05.dealloc.cta_group::2.sync.aligned.b32 %0, %1;" :: "r"(t), "r"((uint32_t)(n)))
#define TCGEN05_RELINQ_CG2() \
    asm volatile("tcgen05.relinquish_alloc_permit.cta_group::2.sync.aligned;")
#define TCGEN05_COMMIT_MC_CG2(mbar, mask) \
    asm volatile("tcgen05.commit.cta_group::2.mbarrier::arrive::one.shared::cluster.multicast::cluster.b64 [%0], %1;" \
                 :: "r"((uint32_t)(mbar)), "h"((uint16_t)(mask)) : "memory")
#define TCGEN05_FENCE_AFTER()  asm volatile("tcgen05.fence::after_thread_sync;" ::: "memory")
#define TCGEN05_FENCE_BEFORE() asm volatile("tcgen05.fence::before_thread_sync;" ::: "memory")
#define TCGEN05_WAIT_LD()      asm volatile("tcgen05.wait::ld.sync.aligned;" ::: "memory")
#define FENCE_PROXY_ASYNC()    asm volatile("fence.proxy.async;" ::: "memory")
#define CP_ASYNC16(dst, src) \
    asm volatile("cp.async.cg.shared.global [%0], [%1], 16;" :: "r"((uint32_t)(dst)), "l"(src) : "memory")
#define CP_ASYNC_COMMIT() asm volatile("cp.async.commit_group;" ::: "memory")
#define CP_ASYNC_WAIT0()  asm volatile("cp.async.wait_group 0;" ::: "memory")

#define TCGEN05_LD_X32(r, addr) \
    asm volatile("tcgen05.ld.sync.aligned.32x32b.x32.b32 " \
        "{%0, %1, %2, %3, %4, %5, %6, %7, %8, %9, %10, %11, %12, %13, %14, %15, " \
        " %16, %17, %18, %19, %20, %21, %22, %23, %24, %25, %26, %27, %28, %29, %30, %31}, [%32];" \
        : "=r"((r)[0]),  "=r"((r)[1]),  "=r"((r)[2]),  "=r"((r)[3]),  \
          "=r"((r)[4]),  "=r"((r)[5]),  "=r"((r)[6]),  "=r"((r)[7]),  \
          "=r"((r)[8]),  "=r"((r)[9]),  "=r"((r)[10]), "=r"((r)[11]), \
          "=r"((r)[12]), "=r"((r)[13]), "=r"((r)[14]), "=r"((r)[15]), \
          "=r"((r)[16]), "=r"((r)[17]), "=r"((r)[18]), "=r"((r)[19]), \
          "=r"((r)[20]), "=r"((r)[21]), "=r"((r)[22]), "=r"((r)[23]), \
          "=r"((r)[24]), "=r"((r)[25]), "=r"((r)[26]), "=r"((r)[27]), \
          "=r"((r)[28]), "=r"((r)[29]), "=r"((r)[30]), "=r"((r)[31]) \
        : "r"(addr))

// SW128 K-major smem descriptor (layout=2, version=1, SBO=64, LBO=1)
static constexpr u64 DESC_BASE_SW128 =
    (u64(2) << 61) | (u64(1) << 46) | (u64(64) << 32) | (u64(1) << 16);
#define MAKE_DESC(a) (DESC_BASE_SW128 | ((u64)((a) >> 4) & 0x3FFF))

// cg2 bf16 SS MMA: idesc = F32 | BF16 a | BF16 b | (N/8)<<17 | (M/16)<<24
#define MMA_IDESC_CG2 0x10400490u   // M=256 (pair), N=256
__device__ __forceinline__ void mma_f16_ss_cg2(uint32_t d, u64 a, u64 b, uint32_t en) {
    asm volatile("{\n\t.reg .pred p;\n\tsetp.ne.u32 p, %4, 0;\n\t"
        "tcgen05.mma.cta_group::2.kind::f16 [%0], %1, %2, %3, "
        "{%5, %5, %5, %5, %5, %5, %5, %5}, p;\n\t}"
        :: "r"(d), "l"(a), "l"(b), "r"(MMA_IDESC_CG2), "r"(en), "r"(0u) : "memory");
}
#endif  // HAS_TCGEN05

// ---------------- elementwise kernels ---------------------------------------
__global__ void build_S_kernel(float* __restrict__ S, const float* __restrict__ Sf,
                               __nv_bfloat16* __restrict__ ahi, __nv_bfloat16* __restrict__ alo,
                               __nv_bfloat16* __restrict__ bhi, __nv_bfloat16* __restrict__ blo) {
    int idx = blockIdx.x * blockDim.x + threadIdx.x;
    int r = idx >> 11, c = idx & (ND - 1);
    float v = 0.f;
    if (r != c) {
        int rr = r < c ? r : c, cc = r < c ? c : r;
        int f = rr * (2 * ND - rr - 1) / 2 + (cc - rr - 1);
        v = Sf[f];
        if (r > c) v = -v;
    }
    S[idx] = v;
    __nv_bfloat16 h, l;
    split2(v, h, l);  ahi[idx] = h; alo[idx] = l;
    split2(-v, h, l); bhi[idx] = h; blo[idx] = l;   // S^T = -S
}

// W2^T = I/48 - S/384 + S2/3840 - S3/46080 (bf16 split);  T = S2/8 + S/2 (fp32)
__global__ void ew_prep_kernel(__nv_bfloat16* __restrict__ w2hi, __nv_bfloat16* __restrict__ w2lo,
                               float* __restrict__ T,
                               const float* __restrict__ S, const float* __restrict__ S2,
                               const float* __restrict__ S3) {
    int idx = blockIdx.x * blockDim.x + threadIdx.x;
    int r = idx >> 11, c = idx & (ND - 1);
    float s = S[idx], s2 = S2[idx], s3 = S3[idx];
    float w2t = -s3 * (1.f / 46080.f) + s2 * (1.f / 3840.f) - s * (1.f / 384.f);
    if (r == c) w2t += (1.f / 48.f);
    __nv_bfloat16 h, l;
    split2(w2t, h, l); w2hi[idx] = h; w2lo[idx] = l;
    T[idx] = s2 * 0.125f + s * 0.5f;
}

// 32x32 tiled transpose + optional diagonal add + bf16 split
__global__ void transpose_conv(const float* __restrict__ in,
                               __nv_bfloat16* __restrict__ thi, __nv_bfloat16* __restrict__ tlo,
                               float idadd) {
    __shared__ float tile[32][33];
    int bx = blockIdx.x * 32, by = blockIdx.y * 32;
    int tx = threadIdx.x, ty = threadIdx.y;   // 32 x 8
#pragma unroll
    for (int j = 0; j < 4; j++)
        tile[ty + 8 * j][tx] = in[(size_t)(by + ty + 8 * j) * ND + bx + tx];
    __syncthreads();
#pragma unroll
    for (int j = 0; j < 4; j++) {
        int ro = bx + ty + 8 * j, co = by + tx;
        float v = tile[tx][ty + 8 * j];
        if (ro == co) v += idadd;
        __nv_bfloat16 h, l; split2(v, h, l);
        size_t o = (size_t)ro * ND + co;
        thi[o] = h; tlo[o] = l;
    }
}

// row-major fp32 -> hi/lo bf16 (for X)
__global__ void conv_rm(const float* __restrict__ in,
                        __nv_bfloat16* __restrict__ hi, __nv_bfloat16* __restrict__ lo) {
    int i = blockIdx.x * blockDim.x + threadIdx.x;
    float4 v = ((const float4*)in)[i];
    __nv_bfloat16 h0, l0, h1, l1, h2, l2, h3, l3;
    split2(v.x, h0, l0); split2(v.y, h1, l1); split2(v.z, h2, l2); split2(v.w, h3, l3);
    ((__nv_bfloat162*)hi)[2 * i]     = __nv_bfloat162(h0, h1);
    ((__nv_bfloat162*)hi)[2 * i + 1] = __nv_bfloat162(h2, h3);
    ((__nv_bfloat162*)lo)[2 * i]     = __nv_bfloat162(l0, l1);
    ((__nv_bfloat162*)lo)[2 * i + 1] = __nv_bfloat162(l2, l3);
}

// ---------------- GEMM: C = A @ B^T, 2-CTA cluster computes 256x256 tile ----
// Cluster (2,1,1): rank = blockIdx.x & 1. Each CTA holds 128 A-rows and its
// 128 B-rows (N/2 split per cg2 contract). 3-stage cp.async pipeline; leader
// issues cg2 MMAs gated by a cluster "full" mbarrier (count=2); cg2 multicast
// commit fires each CTA's local "done" barrier for buffer reuse.
#define BM 128          // per-CTA M share (pair = 256)
#define BN 256
#define BKB 64
#define SUB 16384                         // one 128x64 bf16 sub-tile
#define STAGE_BY (4 * SUB)                // Ahi,Alo,Bhi,Blo = 64 KB
#define NSTG 3
#define SM_HDR 1024
#define GEMM_SMEM (SM_HDR + NSTG * STAGE_BY)  // 197632 bytes

__global__ void __launch_bounds__(256, 1) __cluster_dims__(2, 1, 1)
gemm_bf3(float* __restrict__ C,
         const __nv_bfloat16* __restrict__ Ahi, const __nv_bfloat16* __restrict__ Alo,
         const __nv_bfloat16* __restrict__ Bhi, const __nv_bfloat16* __restrict__ Blo,
         const float* __restrict__ D, float beta,
         __nv_bfloat16* __restrict__ Chi, __nv_bfloat16* __restrict__ Clo,
         int M, int Nn, int K) {
    extern __shared__ char smem[];
    const int tid = threadIdx.x, wid = tid >> 5, lid = tid & 31;
    const int rank = blockIdx.x & 1;
    const int n0 = (blockIdx.x >> 1) * BN;
    const int m0 = blockIdx.y * 2 * BM + rank * BM;   // this CTA's 128 A-rows
    const int nb = n0 + rank * BM;                    // this CTA's 128 B-rows

#if HAS_TCGEN05
    const uint32_t sb = smem_to_u32(smem);
    // mbarriers: full[s] @ sb+64+8s (leader-resident, count=2),
    //            done[s] @ sb+128+8s (local, count=1)
    if (tid == 0) {
#pragma unroll
        for (int s = 0; s < NSTG; s++) {
            MBARRIER_INIT(sb + 64 + 8 * s, 2);
            MBARRIER_INIT(sb + 128 + 8 * s, 1);
        }
    }
    if (wid == 0) TCGEN05_ALLOC_CG2(sb + 0, 256);
    __syncthreads();
    uint32_t tmem;
    asm volatile("ld.shared.b32 %0, [%1];" : "=r"(tmem) : "r"(sb + 0));
    CLUSTER_SYNC();   // peer mbarriers live before any cluster arrive / MMA

    // per-thread cp.async mapping: 4 chunks of 16B per 128x64 sub-tile
    int swz[4]; size_t ga[4], gb[4];
#pragma unroll
    for (int j = 0; j < 4; j++) {
        int ch = tid + 256 * j;
        int row = ch >> 3, c16 = ch & 7;
        swz[j] = SWZ128(row * 128 + c16 * 16);
        ga[j] = (size_t)(m0 + row) * K + c16 * 8;
        gb[j] = (size_t)(nb + row) * K + c16 * 8;
    }

    int dph[NSTG] = {0, 0, 0};
    int fph[NSTG] = {0, 0, 0};
    const int ktiles = K / BKB;
    for (int t = 0; t < ktiles; t++) {
        const int buf = t % NSTG;
        if (t >= NSTG) {            // buffer reuse gate: prior MMA on buf done
            MBARRIER_WAIT_PARITY(sb + 128 + 8 * buf, dph[buf]);
            dph[buf] ^= 1;
        }
        const int k0 = t * BKB;
        const uint32_t st = sb + SM_HDR + buf * STAGE_BY;
#pragma unroll
        for (int j = 0; j < 4; j++) CP_ASYNC16(st + swz[j],           Ahi + ga[j] + k0);
#pragma unroll
        for (int j = 0; j < 4; j++) CP_ASYNC16(st + SUB + swz[j],     Alo + ga[j] + k0);
#pragma unroll
        for (int j = 0; j < 4; j++) CP_ASYNC16(st + 2 * SUB + swz[j], Bhi + gb[j] + k0);
#pragma unroll
        for (int j = 0; j < 4; j++) CP_ASYNC16(st + 3 * SUB + swz[j], Blo + gb[j] + k0);
        CP_ASYNC_COMMIT();
        CP_ASYNC_WAIT0();
        FENCE_PROXY_ASYNC();
        __syncthreads();
        if (tid == 0) MBAR_ARRIVE_LEADER(sb + 64 + 8 * buf);

        if (rank == 0 && wid == 0) {
            // whole warp polls (keeps elect.sync converged), then one issues
            MBARRIER_WAIT_PARITY(sb + 64 + 8 * buf, fph[buf]);
            fph[buf] ^= 1;
            if (elect_one_pred()) {
                u64 dAh = MAKE_DESC(st);
                u64 dAl = MAKE_DESC(st + SUB);
                u64 dBh = MAKE_DESC(st + 2 * SUB);
                u64 dBl = MAKE_DESC(st + 3 * SUB);
#pragma unroll
                for (int ks = 0; ks < 4; ks++) {
                    mma_f16_ss_cg2(tmem, dAh + 2 * ks, dBh + 2 * ks, !(t == 0 && ks == 0));
                    mma_f16_ss_cg2(tmem, dAh + 2 * ks, dBl + 2 * ks, 1u);
                    mma_f16_ss_cg2(tmem, dAl + 2 * ks, dBh + 2 * ks, 1u);
                }
                TCGEN05_COMMIT_MC_CG2(sb + 128 + 8 * buf, 3);
            }
        }
    }

    // drain: last NSTG commits are still pending
    for (int i = ktiles - NSTG; i < ktiles; i++) {
        const int b = i % NSTG;
        MBARRIER_WAIT_PARITY(sb + 128 + 8 * b, dph[b]);
        dph[b] ^= 1;
    }
    TCGEN05_FENCE_AFTER();

    // epilogue: this CTA's TMEM holds its 128 rows x 256 cols of D
    if (wid < 4) {
        const int m = m0 + wid * 32 + lid;
#pragma unroll 1
        for (int chk = 0; chk < 8; chk++) {
            uint32_t dreg[32];
            TCGEN05_LD_X32(dreg, tmem + chk * 32);
            TCGEN05_WAIT_LD();
            size_t off = (size_t)m * Nn + n0 + chk * 32;
            float v[32];
#pragma unroll
            for (int i = 0; i < 32; i++) v[i] = __uint_as_float(dreg[i]);
            if (D) {
#pragma unroll
                for (int q = 0; q < 8; q++) {
                    float4 d = *(const float4*)(D + off + 4 * q);
                    v[4 * q + 0] += beta * d.x; v[4 * q + 1] += beta * d.y;
                    v[4 * q + 2] += beta * d.z; v[4 * q + 3] += beta * d.w;
                }
            }
#pragma unroll
            for (int q = 0; q < 8; q++)
                *(float4*)(C + off + 4 * q) =
                    make_float4(v[4 * q], v[4 * q + 1], v[4 * q + 2], v[4 * q + 3]);
            if (Chi) {
#pragma unroll
                for (int p = 0; p < 16; p++) {
                    __nv_bfloat16 h0, l0, h1, l1;
                    split2(v[2 * p], h0, l0); split2(v[2 * p + 1], h1, l1);
                    ((__nv_bfloat162*)(Chi + off))[p] = __nv_bfloat162(h0, h1);
                    ((__nv_bfloat162*)(Clo + off))[p] = __nv_bfloat162(l0, l1);
                }
            }
        }
        TCGEN05_FENCE_BEFORE();
    }

    __syncthreads();
    if (tid == 0) {
#pragma unroll
        for (int s = 0; s < NSTG; s++) {
            MBARRIER_INVAL(sb + 64 + 8 * s);
            MBARRIER_INVAL(sb + 128 + 8 * s);
        }
    }
    __syncthreads();
    if (wid == 0) { TCGEN05_RELINQ_CG2(); TCGEN05_DEALLOC_CG2(tmem, 256); }
    CLUSTER_SYNC();   // no CTA exits while peer MMA/SMEM traffic may be live

#else
    // ============== SIMT fallback (base sm_103 target; never runs on GB300) ==
    float* As = (float*)smem;                    // [16][128]  As[k][m]
    float* Bs = (float*)(smem + 16 * 128 * 4);   // [16][128]  Bs[k][n]
    const int tm = (wid & 3) * 32 + (lid >> 3) * 8;
    const int tn_ = (wid >> 2) * 64 + (lid & 7) * 8;
    const int trow = tid >> 1;
    const int tk8  = (tid & 1) * 8;

    for (int h = 0; h < 2; h++) {
        const int n0h = n0 + 128 * h;
        float acc[8][8];
#pragma unroll
        for (int i = 0; i < 8; i++)
#pragma unroll
            for (int j = 0; j < 8; j++) acc[i][j] = 0.f;
        for (int k0 = 0; k0 < K; k0 += 16) {
            {
                size_t base = (size_t)(m0 + trow) * K + k0 + tk8;
                uint4 hh = *(const uint4*)(Ahi + base);
                uint4 ll = *(const uint4*)(Alo + base);
                const __nv_bfloat16* hp = (const __nv_bfloat16*)&hh;
                const __nv_bfloat16* lp = (const __nv_bfloat16*)&ll;
#pragma unroll
                for (int j = 0; j < 8; j++)
                    As[(tk8 + j) * 128 + trow] = __bfloat162float(hp[j]) + __bfloat162float(lp[j]);
            }
            {
                size_t base = (size_t)(n0h + trow) * K + k0 + tk8;
                uint4 hh = *(const uint4*)(Bhi + base);
                uint4 ll = *(const uint4*)(Blo + base);
                const __nv_bfloat16* hp = (const __nv_bfloat16*)&hh;
                const __nv_bfloat16* lp = (const __nv_bfloat16*)&ll;
#pragma unroll
                for (int j = 0; j < 8; j++)
                    Bs[(tk8 + j) * 128 + trow] = __bfloat162float(hp[j]) + __bfloat162float(lp[j]);
            }
            __syncthreads();
#pragma unroll
            for (int kk = 0; kk < 16; kk++) {
                float a[8], b[8];
#pragma unroll
                for (int i = 0; i < 8; i++) a[i] = As[kk * 128 + tm + i];
#pragma unroll
                for (int j = 0; j < 8; j++) b[j] = Bs[kk * 128 + tn_ + j];
#pragma unroll
                for (int i = 0; i < 8; i++)
#pragma unroll
                    for (int j = 0; j < 8; j++) acc[i][j] += a[i] * b[j];
            }
            __syncthreads();
        }
#pragma unroll
        for (int i = 0; i < 8; i++) {
            size_t off = (size_t)(m0 + tm + i) * Nn + n0h + tn_;
            float v[8];
#pragma unroll
            for (int j = 0; j < 8; j++) v[j] = acc[i][j];
            if (D) {
#pragma unroll
                for (int j = 0; j < 8; j++) v[j] += beta * D[off + j];
            }
#pragma unroll
            for (int j = 0; j < 8; j++) C[off + j] = v[j];
            if (Chi) {
#pragma unroll
                for (int p = 0; p < 4; p++) {
                    __nv_bfloat16 h0, l0, h1, l1;
                    split2(v[2 * p], h0, l0); split2(v[2 * p + 1], h1, l1);
                    ((__nv_bfloat162*)(Chi + off))[p] = __nv_bfloat162(h0, h1);
                    ((__nv_bfloat162*)(Clo + off))[p] = __nv_bfloat162(l0, l1);
                }
            }
        }
        __syncthreads();
    }
#endif
}

// ---------------- launch -----------------------------------------------------
extern "C" void kernel_launch(void* const* d_in, const int* in_sizes, int n_in,
                              void* d_out, int out_size) {
    const float* X  = (const float*)d_in[0];   // [8192, 2048]
    const float* Sf = (const float*)d_in[1];
    float* Y = (float*)d_out;

    cudaFuncSetAttribute(gemm_bf3, cudaFuncAttributeMaxDynamicSharedMemorySize, GEMM_SMEM);

    float *S, *S2, *S3, *T, *F, *Wf;
    cudaGetSymbolAddress((void**)&S, g_S);   cudaGetSymbolAddress((void**)&S2, g_S2);
    cudaGetSymbolAddress((void**)&S3, g_S3); cudaGetSymbolAddress((void**)&T, g_T);
    cudaGetSymbolAddress((void**)&F, g_F);   cudaGetSymbolAddress((void**)&Wf, g_Wf);
    __nv_bfloat16 *sAh, *sAl, *sBh, *sBl, *s2h, *s2l, *s3h, *s3l;
    __nv_bfloat16 *w2h, *w2l, *fh, *fl, *fth, *ftl, *wfh, *wfl, *xh, *xl;
    cudaGetSymbolAddress((void**)&sAh, g_sA_hi);  cudaGetSymbolAddress((void**)&sAl, g_sA_lo);
    cudaGetSymbolAddress((void**)&sBh, g_sB_hi);  cudaGetSymbolAddress((void**)&sBl, g_sB_lo);
    cudaGetSymbolAddress((void**)&s2h, g_s2_hi);  cudaGetSymbolAddress((void**)&s2l, g_s2_lo);
    cudaGetSymbolAddress((void**)&s3h, g_s3_hi);  cudaGetSymbolAddress((void**)&s3l, g_s3_lo);
    cudaGetSymbolAddress((void**)&w2h, g_w2t_hi); cudaGetSymbolAddress((void**)&w2l, g_w2t_lo);
    cudaGetSymbolAddress((void**)&fh, g_f_hi);    cudaGetSymbolAddress((void**)&fl, g_f_lo);
    cudaGetSymbolAddress((void**)&fth, g_ft_hi);  cudaGetSymbolAddress((void**)&ftl, g_ft_lo);
    cudaGetSymbolAddress((void**)&wfh, g_wft_hi); cudaGetSymbolAddress((void**)&wfl, g_wft_lo);
    cudaGetSymbolAddress((void**)&xh, g_x_hi);    cudaGetSymbolAddress((void**)&xl, g_x_lo);

    const int EW_BLOCKS = NSQ / 256;
    build_S_kernel<<<EW_BLOCKS, 256>>>(S, Sf, sAh, sAl, sBh, sBl);

    // grid.x = 2 * n_blocks (cluster pairs along x); grid.y = M / 256
    dim3 gSq(2 * (ND / BN), ND / 256);   // (16, 8)
    // S2 = S @ S
    gemm_bf3<<<gSq, 256, GEMM_SMEM>>>(S2, sAh, sAl, sBh, sBl, nullptr, 0.f, s2h, s2l, ND, ND, ND);
    // S3 = S2 @ S
    gemm_bf3<<<gSq, 256, GEMM_SMEM>>>(S3, s2h, s2l, sBh, sBl, nullptr, 0.f, s3h, s3l, ND, ND, ND);
    // W2^T (bf16) and T = Finit
    ew_prep_kernel<<<EW_BLOCKS, 256>>>(w2h, w2l, T, S, S2, S3);
    // F = S3 @ W2 + T
    gemm_bf3<<<gSq, 256, GEMM_SMEM>>>(F, s3h, s3l, w2h, w2l, T, 1.f, fh, fl, ND, ND, ND);
    // F^T bf16
    dim3 gT(ND / 32, ND / 32), bT(32, 8);
    transpose_conv<<<gT, bT>>>(F, fth, ftl, 0.f);
    // Wf = F @ F + 2F
    gemm_bf3<<<gSq, 256, GEMM_SMEM>>>(Wf, fh, fl, fth, ftl, F, 2.f, nullptr, nullptr, ND, ND, ND);
    // (Wf + I)^T bf16  (identity folded in -> big GEMM needs no D term)
    transpose_conv<<<gT, bT>>>(Wf, wfh, wfl, 1.f);
    // X -> hi/lo bf16
    conv_rm<<<(NB * ND / 4) / 256, 256>>>(X, xh, xl);
    // Y = X @ (Wf + I)
    dim3 gX(2 * (ND / BN), NB / 256);    // (16, 32)
    gemm_bf3<<<gX, 256, GEMM_SMEM>>>(Y, xh, xl, wfh, wfl, nullptr, 0.f, nullptr, nullptr, NB, ND, ND);
}